// round 15
// baseline (speedup 1.0000x reference)
#include <cuda_runtime.h>
#include <cuda_fp16.h>
#include <cstdint>

typedef uint32_t u32;

#define A_TOT  256
#define D_IN   39
#define H      50
#define BLK    128
#define TPB    4            // row-tiles of 128 per block
#define S1I    48           // interleaved B1 row stride (words)
#define S2I    80           // interleaved B2 row stride (words)

__device__ __forceinline__ u32 pack_h2(float a, float b) {
    __half2 h = __floats2half2_rn(a, b);
    return *reinterpret_cast<u32*>(&h);
}
__device__ __forceinline__ u32 h2tanh(u32 a) {
    u32 d; asm("tanh.approx.f16x2 %0, %1;" : "=r"(d) : "r"(a)); return d;
}
// packed silu: hv = 0.5*v (half2); silu(v) = hv*(1+tanh(hv)) = hfma2(hv, t, hv)
__device__ __forceinline__ u32 silu_from_half(u32 hv) {
    u32 th = h2tanh(hv);
    __half2 r = __hfma2(*reinterpret_cast<__half2*>(&hv),
                        *reinterpret_cast<__half2*>(&th),
                        *reinterpret_cast<__half2*>(&hv));
    return *reinterpret_cast<u32*>(&r);
}
// hv = 0.5*pack(c0,c1) + prepacked 0.5*bias
__device__ __forceinline__ u32 half_bias(float c0, float c1, u32 bp) {
    const u32 h05 = 0x38003800u;
    u32 pc = pack_h2(c0, c1);
    __half2 r = __hfma2(*reinterpret_cast<__half2*>(&pc),
                        *reinterpret_cast<const __half2*>(&h05),
                        *reinterpret_cast<__half2*>(&bp));
    return *reinterpret_cast<u32*>(&r);
}
__device__ __forceinline__ void wsplit2(float v0, float v1, u32& hw, u32& lw) {
    float h0 = __half2float(__float2half_rn(v0));
    float h1 = __half2float(__float2half_rn(v1));
    hw = pack_h2(h0, h1);
    lw = pack_h2(v0 - h0, v1 - h1);
}

// NOTE: non-volatile asm — outputs are used, so not eliminated, and ptxas is
// free to schedule/interleave MMAs with loads and with each other.
#define MMA(Cb, A0, A1, A2, A3, B0, B1)                                  \
    asm("mma.sync.aligned.m16n8k16.row.col.f32.f16.f16.f32 "             \
        "{%0,%1,%2,%3}, {%4,%5,%6,%7}, {%8,%9}, {%0,%1,%2,%3};"          \
        : "+f"(Cb[0]), "+f"(Cb[1]), "+f"(Cb[2]), "+f"(Cb[3])             \
        : "r"(A0), "r"(A1), "r"(A2), "r"(A3), "r"(B0), "r"(B1))

#define MMA8(Cb, A0, A1, B0)                                             \
    asm("mma.sync.aligned.m16n8k8.row.col.f32.f16.f16.f32 "              \
        "{%0,%1,%2,%3}, {%4,%5}, {%6}, {%0,%1,%2,%3};"                   \
        : "+f"(Cb[0]), "+f"(Cb[1]), "+f"(Cb[2]), "+f"(Cb[3])             \
        : "r"(A0), "r"(A1), "r"(B0))

__global__ __launch_bounds__(BLK, 4)
void atomic_mlp_mma11(const float* __restrict__ desc,
                      const int*   __restrict__ numbers,
                      const float* __restrict__ W1, const float* __restrict__ b1,
                      const float* __restrict__ W2, const float* __restrict__ b2,
                      const float* __restrict__ W3, const float* __restrict__ b3,
                      float* __restrict__ out)
{
    __shared__ __align__(16) u32 sB1[56 * S1I];        // 10752 B (hi/lo interleaved)
    __shared__ __align__(16) u32 sB2[56 * S2I];        // 17920 B
    __shared__ float sraw[D_IN * H + H * H];           // 17800 B
    __shared__ u32 b1p[28], b2p[28];                   // 0.5*bias packed half2 per col-pair
    __shared__ float w3v[56];
    __shared__ float b3s;

    const int t   = threadIdx.x;
    const int wid = t >> 5;
    const int lid = t & 31;
    const int g   = lid >> 2;
    const int tq  = lid & 3;
    const int a   = blockIdx.x;
    const int s   = numbers[a];
    const int shift = a & 1;               // K-permutation: col = (k + shift) % 39

    const size_t rs   = (size_t)A_TOT * D_IN;
    const size_t acol = (size_t)a * D_IN;

    // ---- stage raw weights (coalesced, once per block) ----
    #pragma unroll
    for (int j = 0; j < 16; j++) {
        int i = t + j * BLK;
        if (i < D_IN * H) sraw[i] = W1[s * D_IN * H + i];
    }
    #pragma unroll
    for (int j = 0; j < 20; j++) {
        int i = t + j * BLK;
        if (i < H * H) sraw[D_IN * H + i] = W2[s * H * H + i];
    }
    if (t < 28) {
        int c0 = 2 * t, c1 = 2 * t + 1;
        float v0 = (c0 < H) ? 0.5f * b1[s * H + c0] : 0.0f;
        float v1 = (c1 < H) ? 0.5f * b1[s * H + c1] : 0.0f;
        b1p[t] = pack_h2(v0, v1);
        v0 = (c0 < H) ? 0.5f * b2[s * H + c0] : 0.0f;
        v1 = (c1 < H) ? 0.5f * b2[s * H + c1] : 0.0f;
        b2p[t] = pack_h2(v0, v1);
    }
    if (t >= 64 && t < 120) {
        int c = t - 64;
        w3v[c] = (c < H) ? W3[s * H + c] : 0.0f;
    }
    if (t == 0) b3s = b3[s];

    // ---- prefetch tile 0's A fragments via LDG.64 (K-permuted, as R10) ----
    u32 ahn1[2][2][4];   // kk=0,1 full k16
    u32 ahn2[2][2];      // kk=2 k8 (K 32..39)
    {
        const int R0 = (blockIdx.y * TPB) * 128 + wid * 32;
        #pragma unroll
        for (int q = 0; q < 4; q++) {
            int r = R0 + (q >> 1) * 16 + (q & 1) * 8 + g;
            const float* rp = desc + (size_t)r * rs + acol;
            const float2* rp2 = reinterpret_cast<const float2*>(rp + shift);  // 8B-aligned
            int m = q >> 1, o = q & 1;
            float2 v0 = rp2[tq];
            float2 v1 = rp2[tq + 4];
            float2 v2 = rp2[tq + 8];
            float2 v3 = rp2[tq + 12];
            float2 v4 = (tq < 3) ? rp2[tq + 16]
                                 : make_float2(rp[shift ? 0 : 38], 0.0f);
            ahn1[0][m][o]     = pack_h2(v0.x, v0.y);
            ahn1[0][m][2 + o] = pack_h2(v1.x, v1.y);
            ahn1[1][m][o]     = pack_h2(v2.x, v2.y);
            ahn1[1][m][2 + o] = pack_h2(v3.x, v3.y);
            ahn2[m][o]        = pack_h2(v4.x, v4.y);
        }
    }
    __syncthreads();

    // ---- build split-transposed, interleaved weight tiles ----
    // B1 uses the same K-permutation: col(k) = (k + shift) % 39.
    // k16 chunks: hi at p, lo at p+2 (uint4 read). k8 tail: hi at p, lo at p+1 (uint2 read).
    #pragma unroll
    for (int j = 0; j < 11; j++) {
        int i = t + j * BLK;
        if (i < 56 * 24) {
            int n = i / 24, w = i % 24, k0 = 2 * w;
            int c0 = k0 + shift;     if (c0 >= D_IN) c0 = 0;
            int c1 = k0 + 1 + shift; if (c1 >= D_IN) c1 = 0;
            float v0 = (k0     < D_IN && n < H) ? sraw[c0 * H + n] : 0.0f;
            float v1 = (k0 + 1 < D_IN && n < H) ? sraw[c1 * H + n] : 0.0f;
            u32 hw, lw; wsplit2(v0, v1, hw, lw);
            int kk = w >> 3, jj = w & 7;
            if (kk < 2) {
                int p = n * S1I + kk * 16 + (jj & 3) * 4 + (jj >> 2);
                sB1[p]     = hw;
                sB1[p + 2] = lw;
            } else if (jj < 4) {
                int p = n * S1I + 32 + jj * 4;
                sB1[p]     = hw;
                sB1[p + 1] = lw;
            }
        }
    }
    #pragma unroll
    for (int j = 0; j < 14; j++) {
        int i = t + j * BLK;               // exactly 56*32
        int n = i / 32, w = i % 32, k0 = 2 * w;
        float v0 = (k0     < H && n < H) ? sraw[D_IN * H + k0 * H + n]       : 0.0f;
        float v1 = (k0 + 1 < H && n < H) ? sraw[D_IN * H + (k0 + 1) * H + n] : 0.0f;
        u32 hw, lw; wsplit2(v0, v1, hw, lw);
        int kk = w >> 3, jj = w & 7;
        if (kk < 3) {
            int p = n * S2I + kk * 16 + (jj & 3) * 4 + (jj >> 2);
            sB2[p]     = hw;
            sB2[p + 2] = lw;
        } else if (jj < 4) {
            int p = n * S2I + 48 + jj * 4;
            sB2[p]     = hw;
            sB2[p + 1] = lw;
        }
    }
    __syncthreads();

    // ================= tile loop (barrier-free body) =================
    #pragma unroll 1
    for (int it = 0; it < TPB; it++) {
        // ---- layer 1: kk=0,1 k16; kk=2 k8 (A frags used directly from ahn) ----
        float c[56];
        #pragma unroll
        for (int i = 0; i < 56; i++) c[i] = 0.0f;

        #pragma unroll
        for (int kk = 0; kk < 2; kk++)
            #pragma unroll
            for (int n = 0; n < 7; n++) {
                const uint4 b = *reinterpret_cast<const uint4*>(
                    &sB1[(n * 8 + g) * S1I + kk * 16 + 4 * tq]);
                float* C0 = &c[(0 * 7 + n) * 4];
                float* C1 = &c[(1 * 7 + n) * 4];
                // interleaved: dependent hi->lo pairs separated by independent MMA
                MMA(C0, ahn1[kk][0][0], ahn1[kk][0][1], ahn1[kk][0][2], ahn1[kk][0][3], b.x, b.y);
                MMA(C1, ahn1[kk][1][0], ahn1[kk][1][1], ahn1[kk][1][2], ahn1[kk][1][3], b.x, b.y);
                MMA(C0, ahn1[kk][0][0], ahn1[kk][0][1], ahn1[kk][0][2], ahn1[kk][0][3], b.z, b.w);
                MMA(C1, ahn1[kk][1][0], ahn1[kk][1][1], ahn1[kk][1][2], ahn1[kk][1][3], b.z, b.w);
            }
        #pragma unroll
        for (int n = 0; n < 7; n++) {
            const uint2 b = *reinterpret_cast<const uint2*>(
                &sB1[(n * 8 + g) * S1I + 32 + 4 * tq]);
            float* C0 = &c[(0 * 7 + n) * 4];
            float* C1 = &c[(1 * 7 + n) * 4];
            MMA8(C0, ahn2[0][0], ahn2[0][1], b.x);
            MMA8(C1, ahn2[1][0], ahn2[1][1], b.x);
            MMA8(C0, ahn2[0][0], ahn2[0][1], b.y);
            MMA8(C1, ahn2[1][0], ahn2[1][1], b.y);
        }

        // ---- epilogue 1: packed bias + tanh-silu -> fp16 A2 frags ----
        u32 ch0[14], ch1[14];
        #pragma unroll
        for (int m = 0; m < 2; m++)
            #pragma unroll
            for (int n = 0; n < 7; n++) {
                u32 bp = b1p[n * 4 + tq];
                int idx = (m * 7 + n) * 4;
                ch0[m * 7 + n] = silu_from_half(half_bias(c[idx],     c[idx + 1], bp));
                ch1[m * 7 + n] = silu_from_half(half_bias(c[idx + 2], c[idx + 3], bp));
            }

        // ---- prefetch next tile's A (layer-1 frags dead; hidden behind L2 MMAs) ----
        if (it + 1 < TPB) {
            const int R0n = (blockIdx.y * TPB + it + 1) * 128 + wid * 32;
            #pragma unroll
            for (int q = 0; q < 4; q++) {
                int r = R0n + (q >> 1) * 16 + (q & 1) * 8 + g;
                const float* rp = desc + (size_t)r * rs + acol;
                const float2* rp2 = reinterpret_cast<const float2*>(rp + shift);
                int m = q >> 1, o = q & 1;
                float2 v0 = rp2[tq];
                float2 v1 = rp2[tq + 4];
                float2 v2 = rp2[tq + 8];
                float2 v3 = rp2[tq + 12];
                float2 v4 = (tq < 3) ? rp2[tq + 16]
                                     : make_float2(rp[shift ? 0 : 38], 0.0f);
                ahn1[0][m][o]     = pack_h2(v0.x, v0.y);
                ahn1[0][m][2 + o] = pack_h2(v1.x, v1.y);
                ahn1[1][m][o]     = pack_h2(v2.x, v2.y);
                ahn1[1][m][2 + o] = pack_h2(v3.x, v3.y);
                ahn2[m][o]        = pack_h2(v4.x, v4.y);
            }
        }

        // ---- layer 2: kk=0..2 k16; kk=3 k8 (merged hi/lo tail) ----
        float c2[56];
        #pragma unroll
        for (int i = 0; i < 56; i++) c2[i] = 0.0f;

        #pragma unroll
        for (int kk = 0; kk < 3; kk++) {
            #pragma unroll
            for (int n = 0; n < 7; n++) {
                const uint4 b = *reinterpret_cast<const uint4*>(
                    &sB2[(n * 8 + g) * S2I + kk * 16 + 4 * tq]);
                float* C0 = &c2[(0 * 7 + n) * 4];
                float* C1 = &c2[(1 * 7 + n) * 4];
                MMA(C0, ch0[0 * 7 + 2 * kk], ch1[0 * 7 + 2 * kk],
                        ch0[0 * 7 + 2 * kk + 1], ch1[0 * 7 + 2 * kk + 1], b.x, b.y);
                MMA(C1, ch0[1 * 7 + 2 * kk], ch1[1 * 7 + 2 * kk],
                        ch0[1 * 7 + 2 * kk + 1], ch1[1 * 7 + 2 * kk + 1], b.x, b.y);
                MMA(C0, ch0[0 * 7 + 2 * kk], ch1[0 * 7 + 2 * kk],
                        ch0[0 * 7 + 2 * kk + 1], ch1[0 * 7 + 2 * kk + 1], b.z, b.w);
                MMA(C1, ch0[1 * 7 + 2 * kk], ch1[1 * 7 + 2 * kk],
                        ch0[1 * 7 + 2 * kk + 1], ch1[1 * 7 + 2 * kk + 1], b.z, b.w);
            }
        }
        #pragma unroll
        for (int n = 0; n < 7; n++) {
            const uint2 b = *reinterpret_cast<const uint2*>(
                &sB2[(n * 8 + g) * S2I + 48 + 4 * tq]);
            float* C0 = &c2[(0 * 7 + n) * 4];
            float* C1 = &c2[(1 * 7 + n) * 4];
            MMA8(C0, ch0[0 * 7 + 6], ch1[0 * 7 + 6], b.x);
            MMA8(C1, ch0[1 * 7 + 6], ch1[1 * 7 + 6], b.x);
            MMA8(C0, ch0[0 * 7 + 6], ch1[0 * 7 + 6], b.y);
            MMA8(C1, ch0[1 * 7 + 6], ch1[1 * 7 + 6], b.y);
        }

        // ---- epilogue 2: packed silu, fp32 dot W3, reduce, store ----
        float sum[4] = {0.0f, 0.0f, 0.0f, 0.0f};
        #pragma unroll
        for (int m = 0; m < 2; m++)
            #pragma unroll
            for (int n = 0; n < 7; n++) {
                u32 bp = b2p[n * 4 + tq];
                int col = n * 8 + 2 * tq;
                float w30 = w3v[col], w31 = w3v[col + 1];
                int idx = (m * 7 + n) * 4;
                u32 s0 = silu_from_half(half_bias(c2[idx],     c2[idx + 1], bp));
                u32 s1 = silu_from_half(half_bias(c2[idx + 2], c2[idx + 3], bp));
                float2 F0 = __half22float2(*reinterpret_cast<__half2*>(&s0));
                float2 F1 = __half22float2(*reinterpret_cast<__half2*>(&s1));
                sum[m * 2 + 0] += F0.x * w30 + F0.y * w31;
                sum[m * 2 + 1] += F1.x * w30 + F1.y * w31;
            }
        #pragma unroll
        for (int q = 0; q < 4; q++) {
            sum[q] += __shfl_xor_sync(0xffffffffu, sum[q], 1);
            sum[q] += __shfl_xor_sync(0xffffffffu, sum[q], 2);
        }
        if (tq == 0) {
            const int R0 = (blockIdx.y * TPB + it) * 128 + wid * 32;
            float bb = b3s;
            #pragma unroll
            for (int q = 0; q < 4; q++) {
                int r = R0 + (q >> 1) * 16 + (q & 1) * 8 + g;
                out[(size_t)r * A_TOT + a] = sum[q] + bb;
            }
        }
    }
}

extern "C" void kernel_launch(void* const* d_in, const int* in_sizes, int n_in,
                              void* d_out, int out_size)
{
    const float* desc    = (const float*)d_in[0];
    const int*   numbers = (const int*)  d_in[1];
    const float* W1      = (const float*)d_in[2];
    const float* b1      = (const float*)d_in[3];
    const float* W2      = (const float*)d_in[4];
    const float* b2      = (const float*)d_in[5];
    const float* W3      = (const float*)d_in[6];
    const float* b3      = (const float*)d_in[7];
    float* out = (float*)d_out;

    const int N = in_sizes[0] / (A_TOT * D_IN);   // 4096
    dim3 grid(A_TOT, N / (128 * TPB));            // 256 x 8
    atomic_mlp_mma11<<<grid, BLK>>>(desc, numbers, W1, b1, W2, b2, W3, b3, out);
}

// round 16
// speedup vs baseline: 1.3389x; 1.3389x over previous
#include <cuda_runtime.h>
#include <cuda_fp16.h>
#include <cstdint>

typedef uint32_t u32;

#define A_TOT  256
#define D_IN   39
#define H      50
#define BLK    128
#define TPB    4            // row-tiles of 128 per block
#define S1I    48           // interleaved B1 row stride (words)
#define S2I    80           // interleaved B2 row stride (words)

__device__ __forceinline__ u32 pack_h2(float a, float b) {
    __half2 h = __floats2half2_rn(a, b);
    return *reinterpret_cast<u32*>(&h);
}
__device__ __forceinline__ u32 h2tanh(u32 a) {
    u32 d; asm("tanh.approx.f16x2 %0, %1;" : "=r"(d) : "r"(a)); return d;
}
// packed silu: hv = 0.5*v (half2); silu(v) = hv*(1+tanh(hv)) = hfma2(hv, t, hv)
__device__ __forceinline__ u32 silu_from_half(u32 hv) {
    u32 th = h2tanh(hv);
    __half2 r = __hfma2(*reinterpret_cast<__half2*>(&hv),
                        *reinterpret_cast<__half2*>(&th),
                        *reinterpret_cast<__half2*>(&hv));
    return *reinterpret_cast<u32*>(&r);
}
// hv = 0.5*pack(c0,c1) + prepacked 0.5*bias
__device__ __forceinline__ u32 half_bias(float c0, float c1, u32 bp) {
    const u32 h05 = 0x38003800u;
    u32 pc = pack_h2(c0, c1);
    __half2 r = __hfma2(*reinterpret_cast<__half2*>(&pc),
                        *reinterpret_cast<const __half2*>(&h05),
                        *reinterpret_cast<__half2*>(&bp));
    return *reinterpret_cast<u32*>(&r);
}
__device__ __forceinline__ void wsplit2(float v0, float v1, u32& hw, u32& lw) {
    float h0 = __half2float(__float2half_rn(v0));
    float h1 = __half2float(__float2half_rn(v1));
    hw = pack_h2(h0, h1);
    lw = pack_h2(v0 - h0, v1 - h1);
}

// volatile: instruction order is pinned exactly as written (R15 showed that
// freeing ptxas here blows past the 128-reg cap and spills).
#define MMA(Cb, A0, A1, A2, A3, B0, B1)                                  \
    asm volatile("mma.sync.aligned.m16n8k16.row.col.f32.f16.f16.f32 "    \
                 "{%0,%1,%2,%3}, {%4,%5,%6,%7}, {%8,%9}, {%0,%1,%2,%3};" \
                 : "+f"(Cb[0]), "+f"(Cb[1]), "+f"(Cb[2]), "+f"(Cb[3])    \
                 : "r"(A0), "r"(A1), "r"(A2), "r"(A3), "r"(B0), "r"(B1))

#define MMA8(Cb, A0, A1, B0)                                             \
    asm volatile("mma.sync.aligned.m16n8k8.row.col.f32.f16.f16.f32 "     \
                 "{%0,%1,%2,%3}, {%4,%5}, {%6}, {%0,%1,%2,%3};"          \
                 : "+f"(Cb[0]), "+f"(Cb[1]), "+f"(Cb[2]), "+f"(Cb[3])    \
                 : "r"(A0), "r"(A1), "r"(B0))

__global__ __launch_bounds__(BLK, 4)
void atomic_mlp_mma12(const float* __restrict__ desc,
                      const int*   __restrict__ numbers,
                      const float* __restrict__ W1, const float* __restrict__ b1,
                      const float* __restrict__ W2, const float* __restrict__ b2,
                      const float* __restrict__ W3, const float* __restrict__ b3,
                      float* __restrict__ out)
{
    __shared__ __align__(16) u32 sB1[56 * S1I];        // 10752 B (hi/lo interleaved)
    __shared__ __align__(16) u32 sB2[56 * S2I];        // 17920 B
    __shared__ float sraw[D_IN * H + H * H];           // 17800 B
    __shared__ u32 b1p[28], b2p[28];                   // 0.5*bias packed half2 per col-pair
    __shared__ float w3v[56];
    __shared__ float b3s;

    const int t   = threadIdx.x;
    const int wid = t >> 5;
    const int lid = t & 31;
    const int g   = lid >> 2;
    const int tq  = lid & 3;
    const int a   = blockIdx.x;
    const int s   = numbers[a];
    const int shift = a & 1;               // K-permutation: col = (k + shift) % 39

    const size_t rs   = (size_t)A_TOT * D_IN;
    const size_t acol = (size_t)a * D_IN;

    // ---- stage raw weights (coalesced, once per block) ----
    #pragma unroll
    for (int j = 0; j < 16; j++) {
        int i = t + j * BLK;
        if (i < D_IN * H) sraw[i] = W1[s * D_IN * H + i];
    }
    #pragma unroll
    for (int j = 0; j < 20; j++) {
        int i = t + j * BLK;
        if (i < H * H) sraw[D_IN * H + i] = W2[s * H * H + i];
    }
    if (t < 28) {
        int c0 = 2 * t, c1 = 2 * t + 1;
        float v0 = (c0 < H) ? 0.5f * b1[s * H + c0] : 0.0f;
        float v1 = (c1 < H) ? 0.5f * b1[s * H + c1] : 0.0f;
        b1p[t] = pack_h2(v0, v1);
        v0 = (c0 < H) ? 0.5f * b2[s * H + c0] : 0.0f;
        v1 = (c1 < H) ? 0.5f * b2[s * H + c1] : 0.0f;
        b2p[t] = pack_h2(v0, v1);
    }
    if (t >= 64 && t < 120) {
        int c = t - 64;
        w3v[c] = (c < H) ? W3[s * H + c] : 0.0f;
    }
    if (t == 0) b3s = b3[s];

    // ---- prefetch tile 0's A fragments via LDG.64 (K-permuted) ----
    u32 ahn1[2][2][4];   // kk=0,1 full k16
    u32 ahn2[2][2];      // kk=2 k8 (K 32..39)
    {
        const int R0 = (blockIdx.y * TPB) * 128 + wid * 32;
        #pragma unroll
        for (int q = 0; q < 4; q++) {
            int r = R0 + (q >> 1) * 16 + (q & 1) * 8 + g;
            const float* rp = desc + (size_t)r * rs + acol;
            const float2* rp2 = reinterpret_cast<const float2*>(rp + shift);  // 8B-aligned
            int m = q >> 1, o = q & 1;
            float2 v0 = rp2[tq];
            float2 v1 = rp2[tq + 4];
            float2 v2 = rp2[tq + 8];
            float2 v3 = rp2[tq + 12];
            float2 v4 = (tq < 3) ? rp2[tq + 16]
                                 : make_float2(rp[shift ? 0 : 38], 0.0f);
            ahn1[0][m][o]     = pack_h2(v0.x, v0.y);
            ahn1[0][m][2 + o] = pack_h2(v1.x, v1.y);
            ahn1[1][m][o]     = pack_h2(v2.x, v2.y);
            ahn1[1][m][2 + o] = pack_h2(v3.x, v3.y);
            ahn2[m][o]        = pack_h2(v4.x, v4.y);
        }
    }
    __syncthreads();

    // ---- build split-transposed, interleaved weight tiles ----
    // B1 uses the same K-permutation: col(k) = (k + shift) % 39.
    // k16 chunks: hi at p, lo at p+2 (uint4 read). k8 tail: hi at p, lo at p+1 (uint2 read).
    #pragma unroll
    for (int j = 0; j < 11; j++) {
        int i = t + j * BLK;
        if (i < 56 * 24) {
            int n = i / 24, w = i % 24, k0 = 2 * w;
            int c0 = k0 + shift;     if (c0 >= D_IN) c0 = 0;
            int c1 = k0 + 1 + shift; if (c1 >= D_IN) c1 = 0;
            float v0 = (k0     < D_IN && n < H) ? sraw[c0 * H + n] : 0.0f;
            float v1 = (k0 + 1 < D_IN && n < H) ? sraw[c1 * H + n] : 0.0f;
            u32 hw, lw; wsplit2(v0, v1, hw, lw);
            int kk = w >> 3, jj = w & 7;
            if (kk < 2) {
                int p = n * S1I + kk * 16 + (jj & 3) * 4 + (jj >> 2);
                sB1[p]     = hw;
                sB1[p + 2] = lw;
            } else if (jj < 4) {
                int p = n * S1I + 32 + jj * 4;
                sB1[p]     = hw;
                sB1[p + 1] = lw;
            }
        }
    }
    #pragma unroll
    for (int j = 0; j < 14; j++) {
        int i = t + j * BLK;               // exactly 56*32
        int n = i / 32, w = i % 32, k0 = 2 * w;
        float v0 = (k0     < H && n < H) ? sraw[D_IN * H + k0 * H + n]       : 0.0f;
        float v1 = (k0 + 1 < H && n < H) ? sraw[D_IN * H + (k0 + 1) * H + n] : 0.0f;
        u32 hw, lw; wsplit2(v0, v1, hw, lw);
        int kk = w >> 3, jj = w & 7;
        if (kk < 3) {
            int p = n * S2I + kk * 16 + (jj & 3) * 4 + (jj >> 2);
            sB2[p]     = hw;
            sB2[p + 2] = lw;
        } else if (jj < 4) {
            int p = n * S2I + 48 + jj * 4;
            sB2[p]     = hw;
            sB2[p + 1] = lw;
        }
    }
    __syncthreads();

    // ================= tile loop (barrier-free body) =================
    #pragma unroll 1
    for (int it = 0; it < TPB; it++) {
        // ---- layer 1: kk=0,1 k16; kk=2 k8 ----
        float c[56];
        #pragma unroll
        for (int i = 0; i < 56; i++) c[i] = 0.0f;

        #pragma unroll
        for (int kk = 0; kk < 2; kk++)
            #pragma unroll
            for (int n = 0; n < 7; n++) {
                const uint4 b = *reinterpret_cast<const uint4*>(
                    &sB1[(n * 8 + g) * S1I + kk * 16 + 4 * tq]);
                float* C0 = &c[(0 * 7 + n) * 4];
                float* C1 = &c[(1 * 7 + n) * 4];
                // interleaved: dependent hi->lo pairs separated by independent MMA
                MMA(C0, ahn1[kk][0][0], ahn1[kk][0][1], ahn1[kk][0][2], ahn1[kk][0][3], b.x, b.y);
                MMA(C1, ahn1[kk][1][0], ahn1[kk][1][1], ahn1[kk][1][2], ahn1[kk][1][3], b.x, b.y);
                MMA(C0, ahn1[kk][0][0], ahn1[kk][0][1], ahn1[kk][0][2], ahn1[kk][0][3], b.z, b.w);
                MMA(C1, ahn1[kk][1][0], ahn1[kk][1][1], ahn1[kk][1][2], ahn1[kk][1][3], b.z, b.w);
            }
        #pragma unroll
        for (int n = 0; n < 7; n++) {
            const uint2 b = *reinterpret_cast<const uint2*>(
                &sB1[(n * 8 + g) * S1I + 32 + 4 * tq]);
            float* C0 = &c[(0 * 7 + n) * 4];
            float* C1 = &c[(1 * 7 + n) * 4];
            MMA8(C0, ahn2[0][0], ahn2[0][1], b.x);
            MMA8(C1, ahn2[1][0], ahn2[1][1], b.x);
            MMA8(C0, ahn2[0][0], ahn2[0][1], b.y);
            MMA8(C1, ahn2[1][0], ahn2[1][1], b.y);
        }

        // ---- epilogue 1: packed bias + tanh-silu -> fp16 A2 frags ----
        u32 ch0[14], ch1[14];
        #pragma unroll
        for (int m = 0; m < 2; m++)
            #pragma unroll
            for (int n = 0; n < 7; n++) {
                u32 bp = b1p[n * 4 + tq];
                int idx = (m * 7 + n) * 4;
                ch0[m * 7 + n] = silu_from_half(half_bias(c[idx],     c[idx + 1], bp));
                ch1[m * 7 + n] = silu_from_half(half_bias(c[idx + 2], c[idx + 3], bp));
            }

        // ---- prefetch next tile's A (hidden behind layer-2 MMAs) ----
        if (it + 1 < TPB) {
            const int R0n = (blockIdx.y * TPB + it + 1) * 128 + wid * 32;
            #pragma unroll
            for (int q = 0; q < 4; q++) {
                int r = R0n + (q >> 1) * 16 + (q & 1) * 8 + g;
                const float* rp = desc + (size_t)r * rs + acol;
                const float2* rp2 = reinterpret_cast<const float2*>(rp + shift);
                int m = q >> 1, o = q & 1;
                float2 v0 = rp2[tq];
                float2 v1 = rp2[tq + 4];
                float2 v2 = rp2[tq + 8];
                float2 v3 = rp2[tq + 12];
                float2 v4 = (tq < 3) ? rp2[tq + 16]
                                     : make_float2(rp[shift ? 0 : 38], 0.0f);
                ahn1[0][m][o]     = pack_h2(v0.x, v0.y);
                ahn1[0][m][2 + o] = pack_h2(v1.x, v1.y);
                ahn1[1][m][o]     = pack_h2(v2.x, v2.y);
                ahn1[1][m][2 + o] = pack_h2(v3.x, v3.y);
                ahn2[m][o]        = pack_h2(v4.x, v4.y);
            }
        }

        // ---- layer 2: kk=0..2 k16; kk=3 k8 (merged hi/lo tail) ----
        float c2[56];
        #pragma unroll
        for (int i = 0; i < 56; i++) c2[i] = 0.0f;

        #pragma unroll
        for (int kk = 0; kk < 3; kk++) {
            #pragma unroll
            for (int n = 0; n < 7; n++) {
                const uint4 b = *reinterpret_cast<const uint4*>(
                    &sB2[(n * 8 + g) * S2I + kk * 16 + 4 * tq]);
                float* C0 = &c2[(0 * 7 + n) * 4];
                float* C1 = &c2[(1 * 7 + n) * 4];
                MMA(C0, ch0[0 * 7 + 2 * kk], ch1[0 * 7 + 2 * kk],
                        ch0[0 * 7 + 2 * kk + 1], ch1[0 * 7 + 2 * kk + 1], b.x, b.y);
                MMA(C1, ch0[1 * 7 + 2 * kk], ch1[1 * 7 + 2 * kk],
                        ch0[1 * 7 + 2 * kk + 1], ch1[1 * 7 + 2 * kk + 1], b.x, b.y);
                MMA(C0, ch0[0 * 7 + 2 * kk], ch1[0 * 7 + 2 * kk],
                        ch0[0 * 7 + 2 * kk + 1], ch1[0 * 7 + 2 * kk + 1], b.z, b.w);
                MMA(C1, ch0[1 * 7 + 2 * kk], ch1[1 * 7 + 2 * kk],
                        ch0[1 * 7 + 2 * kk + 1], ch1[1 * 7 + 2 * kk + 1], b.z, b.w);
            }
        }
        #pragma unroll
        for (int n = 0; n < 7; n++) {
            const uint2 b = *reinterpret_cast<const uint2*>(
                &sB2[(n * 8 + g) * S2I + 48 + 4 * tq]);
            float* C0 = &c2[(0 * 7 + n) * 4];
            float* C1 = &c2[(1 * 7 + n) * 4];
            MMA8(C0, ch0[0 * 7 + 6], ch1[0 * 7 + 6], b.x);
            MMA8(C1, ch0[1 * 7 + 6], ch1[1 * 7 + 6], b.x);
            MMA8(C0, ch0[0 * 7 + 6], ch1[0 * 7 + 6], b.y);
            MMA8(C1, ch0[1 * 7 + 6], ch1[1 * 7 + 6], b.y);
        }

        // ---- epilogue 2: packed silu, fp32 dot W3, reduce, store ----
        float sum[4] = {0.0f, 0.0f, 0.0f, 0.0f};
        #pragma unroll
        for (int m = 0; m < 2; m++)
            #pragma unroll
            for (int n = 0; n < 7; n++) {
                u32 bp = b2p[n * 4 + tq];
                int col = n * 8 + 2 * tq;
                float w30 = w3v[col], w31 = w3v[col + 1];
                int idx = (m * 7 + n) * 4;
                u32 s0 = silu_from_half(half_bias(c2[idx],     c2[idx + 1], bp));
                u32 s1 = silu_from_half(half_bias(c2[idx + 2], c2[idx + 3], bp));
                float2 F0 = __half22float2(*reinterpret_cast<__half2*>(&s0));
                float2 F1 = __half22float2(*reinterpret_cast<__half2*>(&s1));
                sum[m * 2 + 0] += F0.x * w30 + F0.y * w31;
                sum[m * 2 + 1] += F1.x * w30 + F1.y * w31;
            }
        #pragma unroll
        for (int q = 0; q < 4; q++) {
            sum[q] += __shfl_xor_sync(0xffffffffu, sum[q], 1);
            sum[q] += __shfl_xor_sync(0xffffffffu, sum[q], 2);
        }
        if (tq == 0) {
            const int R0 = (blockIdx.y * TPB + it) * 128 + wid * 32;
            float bb = b3s;
            #pragma unroll
            for (int q = 0; q < 4; q++) {
                int r = R0 + (q >> 1) * 16 + (q & 1) * 8 + g;
                out[(size_t)r * A_TOT + a] = sum[q] + bb;
            }
        }
    }
}

extern "C" void kernel_launch(void* const* d_in, const int* in_sizes, int n_in,
                              void* d_out, int out_size)
{
    const float* desc    = (const float*)d_in[0];
    const int*   numbers = (const int*)  d_in[1];
    const float* W1      = (const float*)d_in[2];
    const float* b1      = (const float*)d_in[3];
    const float* W2      = (const float*)d_in[4];
    const float* b2      = (const float*)d_in[5];
    const float* W3      = (const float*)d_in[6];
    const float* b3      = (const float*)d_in[7];
    float* out = (float*)d_out;

    const int N = in_sizes[0] / (A_TOT * D_IN);   // 4096
    dim3 grid(A_TOT, N / (128 * TPB));            // 256 x 8
    atomic_mlp_mma12<<<grid, BLK>>>(desc, numbers, W1, b1, W2, b2, W3, b3, out);
}

// round 17
// speedup vs baseline: 1.4128x; 1.0552x over previous
#include <cuda_runtime.h>
#include <cuda_fp16.h>
#include <cstdint>

typedef uint32_t u32;

#define A_TOT  256
#define D_IN   39
#define H      50
#define BLK    256          // 8 warps per block, 2 blocks/SM
#define TPB    4            // row-tiles of 256 per block
#define TILE_R 256          // rows per tile (8 warps x 32)
#define S1I    48           // interleaved B1 row stride (words)
#define S2I    80           // interleaved B2 row stride (words)

__device__ __forceinline__ u32 pack_h2(float a, float b) {
    __half2 h = __floats2half2_rn(a, b);
    return *reinterpret_cast<u32*>(&h);
}
__device__ __forceinline__ u32 h2tanh(u32 a) {
    u32 d; asm("tanh.approx.f16x2 %0, %1;" : "=r"(d) : "r"(a)); return d;
}
// packed silu: hv = 0.5*v (half2); silu(v) = hv*(1+tanh(hv)) = hfma2(hv, t, hv)
__device__ __forceinline__ u32 silu_from_half(u32 hv) {
    u32 th = h2tanh(hv);
    __half2 r = __hfma2(*reinterpret_cast<__half2*>(&hv),
                        *reinterpret_cast<__half2*>(&th),
                        *reinterpret_cast<__half2*>(&hv));
    return *reinterpret_cast<u32*>(&r);
}
// hv = 0.5*pack(c0,c1) + prepacked 0.5*bias
__device__ __forceinline__ u32 half_bias(float c0, float c1, u32 bp) {
    const u32 h05 = 0x38003800u;
    u32 pc = pack_h2(c0, c1);
    __half2 r = __hfma2(*reinterpret_cast<__half2*>(&pc),
                        *reinterpret_cast<const __half2*>(&h05),
                        *reinterpret_cast<__half2*>(&bp));
    return *reinterpret_cast<u32*>(&r);
}
__device__ __forceinline__ void wsplit2(float v0, float v1, u32& hw, u32& lw) {
    float h0 = __half2float(__float2half_rn(v0));
    float h1 = __half2float(__float2half_rn(v1));
    hw = pack_h2(h0, h1);
    lw = pack_h2(v0 - h0, v1 - h1);
}

#define MMA(Cb, A0, A1, A2, A3, B0, B1)                                  \
    asm volatile("mma.sync.aligned.m16n8k16.row.col.f32.f16.f16.f32 "    \
                 "{%0,%1,%2,%3}, {%4,%5,%6,%7}, {%8,%9}, {%0,%1,%2,%3};" \
                 : "+f"(Cb[0]), "+f"(Cb[1]), "+f"(Cb[2]), "+f"(Cb[3])    \
                 : "r"(A0), "r"(A1), "r"(A2), "r"(A3), "r"(B0), "r"(B1))

#define MMA8(Cb, A0, A1, B0)                                             \
    asm volatile("mma.sync.aligned.m16n8k8.row.col.f32.f16.f16.f32 "     \
                 "{%0,%1,%2,%3}, {%4,%5}, {%6}, {%0,%1,%2,%3};"          \
                 : "+f"(Cb[0]), "+f"(Cb[1]), "+f"(Cb[2]), "+f"(Cb[3])    \
                 : "r"(A0), "r"(A1), "r"(B0))

__global__ __launch_bounds__(BLK, 2)
void atomic_mlp_mma13(const float* __restrict__ desc,
                      const int*   __restrict__ numbers,
                      const float* __restrict__ W1, const float* __restrict__ b1,
                      const float* __restrict__ W2, const float* __restrict__ b2,
                      const float* __restrict__ W3, const float* __restrict__ b3,
                      float* __restrict__ out)
{
    __shared__ __align__(16) u32 sB1[56 * S1I];        // 10752 B (hi/lo interleaved)
    __shared__ __align__(16) u32 sB2[56 * S2I];        // 17920 B
    __shared__ float sraw[D_IN * H + H * H];           // 17800 B
    __shared__ u32 b1p[28], b2p[28];                   // 0.5*bias packed half2 per col-pair
    __shared__ float w3v[56];
    __shared__ float b3s;

    const int t   = threadIdx.x;
    const int wid = t >> 5;
    const int lid = t & 31;
    const int g   = lid >> 2;
    const int tq  = lid & 3;
    const int a   = blockIdx.x;
    const int s   = numbers[a];
    const int shift = a & 1;               // K-permutation: col = (k + shift) % 39

    const size_t rs   = (size_t)A_TOT * D_IN;
    const size_t acol = (size_t)a * D_IN;

    // ---- stage raw weights (coalesced, once per block; amortized over 8 warps) ----
    #pragma unroll
    for (int j = 0; j < 8; j++) {
        int i = t + j * BLK;
        if (i < D_IN * H) sraw[i] = W1[s * D_IN * H + i];
    }
    #pragma unroll
    for (int j = 0; j < 10; j++) {
        int i = t + j * BLK;
        if (i < H * H) sraw[D_IN * H + i] = W2[s * H * H + i];
    }
    if (t < 28) {
        int c0 = 2 * t, c1 = 2 * t + 1;
        float v0 = (c0 < H) ? 0.5f * b1[s * H + c0] : 0.0f;
        float v1 = (c1 < H) ? 0.5f * b1[s * H + c1] : 0.0f;
        b1p[t] = pack_h2(v0, v1);
        v0 = (c0 < H) ? 0.5f * b2[s * H + c0] : 0.0f;
        v1 = (c1 < H) ? 0.5f * b2[s * H + c1] : 0.0f;
        b2p[t] = pack_h2(v0, v1);
    }
    if (t >= 64 && t < 120) {
        int c = t - 64;
        w3v[c] = (c < H) ? W3[s * H + c] : 0.0f;
    }
    if (t == 0) b3s = b3[s];

    // ---- prefetch tile 0's A fragments via LDG.64 (K-permuted, R10 body) ----
    u32 ahn1[2][2][4];   // kk=0,1 full k16
    u32 ahn2[2][2];      // kk=2 k8 (K 32..39)
    {
        const int R0 = (blockIdx.y * TPB) * TILE_R + wid * 32;
        #pragma unroll
        for (int q = 0; q < 4; q++) {
            int r = R0 + (q >> 1) * 16 + (q & 1) * 8 + g;
            const float* rp = desc + (size_t)r * rs + acol;
            const float2* rp2 = reinterpret_cast<const float2*>(rp + shift);  // 8B-aligned
            int m = q >> 1, o = q & 1;
            float2 v0 = rp2[tq];
            float2 v1 = rp2[tq + 4];
            float2 v2 = rp2[tq + 8];
            float2 v3 = rp2[tq + 12];
            float2 v4 = (tq < 3) ? rp2[tq + 16]
                                 : make_float2(rp[shift ? 0 : 38], 0.0f);
            ahn1[0][m][o]     = pack_h2(v0.x, v0.y);
            ahn1[0][m][2 + o] = pack_h2(v1.x, v1.y);
            ahn1[1][m][o]     = pack_h2(v2.x, v2.y);
            ahn1[1][m][2 + o] = pack_h2(v3.x, v3.y);
            ahn2[m][o]        = pack_h2(v4.x, v4.y);
        }
    }
    __syncthreads();

    // ---- build split-transposed, interleaved weight tiles (R10 layout) ----
    // B1 uses the same K-permutation: col(k) = (k + shift) % 39.
    #pragma unroll
    for (int j = 0; j < 6; j++) {
        int i = t + j * BLK;
        if (i < 56 * 24) {
            int n = i / 24, w = i % 24, k0 = 2 * w;
            int c0 = k0 + shift;     if (c0 >= D_IN) c0 = 0;
            int c1 = k0 + 1 + shift; if (c1 >= D_IN) c1 = 0;
            float v0 = (k0     < D_IN && n < H) ? sraw[c0 * H + n] : 0.0f;
            float v1 = (k0 + 1 < D_IN && n < H) ? sraw[c1 * H + n] : 0.0f;
            u32 hw, lw; wsplit2(v0, v1, hw, lw);
            int kk = w >> 3, jj = w & 7;
            int p = n * S1I + kk * 16 + (jj & 3) * 4 + (jj >> 2);
            sB1[p]     = hw;
            sB1[p + 2] = lw;
        }
    }
    #pragma unroll
    for (int j = 0; j < 7; j++) {
        int i = t + j * BLK;               // exactly 56*32
        int n = i / 32, w = i % 32, k0 = 2 * w;
        float v0 = (k0     < H && n < H) ? sraw[D_IN * H + k0 * H + n]       : 0.0f;
        float v1 = (k0 + 1 < H && n < H) ? sraw[D_IN * H + (k0 + 1) * H + n] : 0.0f;
        u32 hw, lw; wsplit2(v0, v1, hw, lw);
        int kk = w >> 3, jj = w & 7;
        int p = n * S2I + kk * 16 + (jj & 3) * 4 + (jj >> 2);
        sB2[p]     = hw;
        sB2[p + 2] = lw;
    }
    __syncthreads();

    // ================= tile loop (barrier-free body; identical to R10) =================
    #pragma unroll 1
    for (int it = 0; it < TPB; it++) {
        u32 ah1[2][2][4], ah2[2][2];
        #pragma unroll
        for (int kk = 0; kk < 2; kk++)
            #pragma unroll
            for (int m = 0; m < 2; m++)
                #pragma unroll
                for (int o = 0; o < 4; o++)
                    ah1[kk][m][o] = ahn1[kk][m][o];
        #pragma unroll
        for (int m = 0; m < 2; m++) {
            ah2[m][0] = ahn2[m][0];
            ah2[m][1] = ahn2[m][1];
        }

        // ---- layer 1: kk=0,1 k16; kk=2 k8 ----
        float c[56];
        #pragma unroll
        for (int i = 0; i < 56; i++) c[i] = 0.0f;

        #pragma unroll
        for (int kk = 0; kk < 2; kk++)
            #pragma unroll
            for (int n = 0; n < 7; n++) {
                const uint4 b = *reinterpret_cast<const uint4*>(
                    &sB1[(n * 8 + g) * S1I + kk * 16 + 4 * tq]);
                #pragma unroll
                for (int m = 0; m < 2; m++) {
                    float* C = &c[(m * 7 + n) * 4];
                    MMA(C, ah1[kk][m][0], ah1[kk][m][1], ah1[kk][m][2], ah1[kk][m][3], b.x, b.y);
                    MMA(C, ah1[kk][m][0], ah1[kk][m][1], ah1[kk][m][2], ah1[kk][m][3], b.z, b.w);
                }
            }
        #pragma unroll
        for (int n = 0; n < 7; n++) {
            int p = (n * 8 + g) * S1I + 32 + 4 * tq;
            u32 bh = sB1[p], bl = sB1[p + 2];
            #pragma unroll
            for (int m = 0; m < 2; m++) {
                float* C = &c[(m * 7 + n) * 4];
                MMA8(C, ah2[m][0], ah2[m][1], bh);
                MMA8(C, ah2[m][0], ah2[m][1], bl);
            }
        }

        // ---- epilogue 1: packed bias + tanh-silu -> fp16 A2 frags ----
        u32 ch0[14], ch1[14];
        #pragma unroll
        for (int m = 0; m < 2; m++)
            #pragma unroll
            for (int n = 0; n < 7; n++) {
                u32 bp = b1p[n * 4 + tq];
                int idx = (m * 7 + n) * 4;
                ch0[m * 7 + n] = silu_from_half(half_bias(c[idx],     c[idx + 1], bp));
                ch1[m * 7 + n] = silu_from_half(half_bias(c[idx + 2], c[idx + 3], bp));
            }

        // ---- prefetch next tile's A (hidden behind layer-2 MMAs) ----
        if (it + 1 < TPB) {
            const int R0n = (blockIdx.y * TPB + it + 1) * TILE_R + wid * 32;
            #pragma unroll
            for (int q = 0; q < 4; q++) {
                int r = R0n + (q >> 1) * 16 + (q & 1) * 8 + g;
                const float* rp = desc + (size_t)r * rs + acol;
                const float2* rp2 = reinterpret_cast<const float2*>(rp + shift);
                int m = q >> 1, o = q & 1;
                float2 v0 = rp2[tq];
                float2 v1 = rp2[tq + 4];
                float2 v2 = rp2[tq + 8];
                float2 v3 = rp2[tq + 12];
                float2 v4 = (tq < 3) ? rp2[tq + 16]
                                     : make_float2(rp[shift ? 0 : 38], 0.0f);
                ahn1[0][m][o]     = pack_h2(v0.x, v0.y);
                ahn1[0][m][2 + o] = pack_h2(v1.x, v1.y);
                ahn1[1][m][o]     = pack_h2(v2.x, v2.y);
                ahn1[1][m][2 + o] = pack_h2(v3.x, v3.y);
                ahn2[m][o]        = pack_h2(v4.x, v4.y);
            }
        }

        // ---- layer 2: kk=0..2 k16; kk=3 k8 ----
        float c2[56];
        #pragma unroll
        for (int i = 0; i < 56; i++) c2[i] = 0.0f;

        #pragma unroll
        for (int kk = 0; kk < 3; kk++) {
            #pragma unroll
            for (int n = 0; n < 7; n++) {
                const uint4 b = *reinterpret_cast<const uint4*>(
                    &sB2[(n * 8 + g) * S2I + kk * 16 + 4 * tq]);
                #pragma unroll
                for (int m = 0; m < 2; m++) {
                    float* C = &c2[(m * 7 + n) * 4];
                    MMA(C, ch0[m * 7 + 2 * kk], ch1[m * 7 + 2 * kk],
                           ch0[m * 7 + 2 * kk + 1], ch1[m * 7 + 2 * kk + 1], b.x, b.y);
                    MMA(C, ch0[m * 7 + 2 * kk], ch1[m * 7 + 2 * kk],
                           ch0[m * 7 + 2 * kk + 1], ch1[m * 7 + 2 * kk + 1], b.z, b.w);
                }
            }
        }
        #pragma unroll
        for (int n = 0; n < 7; n++) {
            int p = (n * 8 + g) * S2I + 48 + 4 * tq;
            u32 bh = sB2[p], bl = sB2[p + 2];
            #pragma unroll
            for (int m = 0; m < 2; m++) {
                float* C = &c2[(m * 7 + n) * 4];
                MMA8(C, ch0[m * 7 + 6], ch1[m * 7 + 6], bh);
                MMA8(C, ch0[m * 7 + 6], ch1[m * 7 + 6], bl);
            }
        }

        // ---- epilogue 2: packed silu, fp32 dot W3, reduce, store ----
        float sum[4] = {0.0f, 0.0f, 0.0f, 0.0f};
        #pragma unroll
        for (int m = 0; m < 2; m++)
            #pragma unroll
            for (int n = 0; n < 7; n++) {
                u32 bp = b2p[n * 4 + tq];
                int col = n * 8 + 2 * tq;
                float w30 = w3v[col], w31 = w3v[col + 1];
                int idx = (m * 7 + n) * 4;
                u32 s0 = silu_from_half(half_bias(c2[idx],     c2[idx + 1], bp));
                u32 s1 = silu_from_half(half_bias(c2[idx + 2], c2[idx + 3], bp));
                float2 F0 = __half22float2(*reinterpret_cast<__half2*>(&s0));
                float2 F1 = __half22float2(*reinterpret_cast<__half2*>(&s1));
                sum[m * 2 + 0] += F0.x * w30 + F0.y * w31;
                sum[m * 2 + 1] += F1.x * w30 + F1.y * w31;
            }
        #pragma unroll
        for (int q = 0; q < 4; q++) {
            sum[q] += __shfl_xor_sync(0xffffffffu, sum[q], 1);
            sum[q] += __shfl_xor_sync(0xffffffffu, sum[q], 2);
        }
        if (tq == 0) {
            const int R0 = (blockIdx.y * TPB + it) * TILE_R + wid * 32;
            float bb = b3s;
            #pragma unroll
            for (int q = 0; q < 4; q++) {
                int r = R0 + (q >> 1) * 16 + (q & 1) * 8 + g;
                out[(size_t)r * A_TOT + a] = sum[q] + bb;
            }
        }
    }
}

extern "C" void kernel_launch(void* const* d_in, const int* in_sizes, int n_in,
                              void* d_out, int out_size)
{
    const float* desc    = (const float*)d_in[0];
    const int*   numbers = (const int*)  d_in[1];
    const float* W1      = (const float*)d_in[2];
    const float* b1      = (const float*)d_in[3];
    const float* W2      = (const float*)d_in[4];
    const float* b2      = (const float*)d_in[5];
    const float* W3      = (const float*)d_in[6];
    const float* b3      = (const float*)d_in[7];
    float* out = (float*)d_out;

    const int N = in_sizes[0] / (A_TOT * D_IN);   // 4096
    dim3 grid(A_TOT, N / (TILE_R * TPB));         // 256 x 4 = 1024 blocks
    atomic_mlp_mma13<<<grid, BLK>>>(desc, numbers, W1, b1, W2, b2, W3, b3, out);
}